// round 16
// baseline (speedup 1.0000x reference)
#include <cuda_runtime.h>
#include <cuda_bf16.h>
#include <math_constants.h>
#include <cstdint>

// ---------------- problem constants ----------------
#define C_DIM   512
#define NGROUPS 32
#define GSIZE   16
#define BATCH   4
#define HW      4096
#define NTOK    16384
#define EPS     1e-6f
#define SM_SCALE 0.04419417382415922f   // 512^-0.5
#define QKV_N   1536
#define BM      64                       // CTA m-tile (warp tile 32x32)

typedef __nv_bfloat16 bf16;

// ---------------- device scratch ----------------
__device__ float   g_ps  [BATCH * NGROUPS * 4 * 2];   // partial GN sums
__device__ float   g_mean[BATCH * NGROUPS];
__device__ float   g_rstd[BATCH * NGROUPS];
__device__ bf16    g_hn [NTOK * C_DIM];
__device__ uint8_t g_q8 [(size_t)NTOK * C_DIM];       // e4m3 Q
__device__ uint8_t g_k8 [(size_t)NTOK * C_DIM];       // e4m3 K
__device__ bf16    g_v  [(size_t)NTOK * C_DIM];       // bf16 V
__device__ bf16    g_s  [(size_t)BATCH * HW * HW];    // 128 MB exp(scores)
__device__ bf16    g_o  [NTOK * C_DIM];
__device__ bf16    g_wqkv[QKV_N * C_DIM];             // [n][k]
__device__ bf16    g_wo  [C_DIM * C_DIM];             // [n][k]
__device__ float   g_bqkv[QKV_N];
__device__ float   g_rowsum[NTOK];

// ---------------- helpers ----------------
__device__ __forceinline__ uint32_t smem_u32(const void* p) {
    return (uint32_t)__cvta_generic_to_shared(p);
}
#define CP_ASYNC16(dst, src) \
    asm volatile("cp.async.cg.shared.global [%0], [%1], 16;" :: "r"(dst), "l"(src))
#define CP_COMMIT() asm volatile("cp.async.commit_group;")

#define LDSM4(r0,r1,r2,r3, addr) \
    asm volatile("ldmatrix.sync.aligned.m8n8.x4.shared.b16 {%0,%1,%2,%3}, [%4];" \
        : "=r"(r0),"=r"(r1),"=r"(r2),"=r"(r3) : "r"(addr))
#define LDSM4T(r0,r1,r2,r3, addr) \
    asm volatile("ldmatrix.sync.aligned.m8n8.x4.trans.shared.b16 {%0,%1,%2,%3}, [%4];" \
        : "=r"(r0),"=r"(r1),"=r"(r2),"=r"(r3) : "r"(addr))

__device__ __forceinline__ void mma_bf16(float& c0, float& c1, float& c2, float& c3,
                                         uint32_t a0, uint32_t a1, uint32_t a2, uint32_t a3,
                                         uint32_t b0, uint32_t b1) {
    asm volatile(
        "mma.sync.aligned.m16n8k16.row.col.f32.bf16.bf16.f32 "
        "{%0,%1,%2,%3}, {%4,%5,%6,%7}, {%8,%9}, {%0,%1,%2,%3};"
        : "+f"(c0), "+f"(c1), "+f"(c2), "+f"(c3)
        : "r"(a0), "r"(a1), "r"(a2), "r"(a3), "r"(b0), "r"(b1));
}
__device__ __forceinline__ void mma_e4m3(float& c0, float& c1, float& c2, float& c3,
                                         uint32_t a0, uint32_t a1, uint32_t a2, uint32_t a3,
                                         uint32_t b0, uint32_t b1) {
    asm volatile(
        "mma.sync.aligned.m16n8k32.row.col.f32.e4m3.e4m3.f32 "
        "{%0,%1,%2,%3}, {%4,%5,%6,%7}, {%8,%9}, {%0,%1,%2,%3};"
        : "+f"(c0), "+f"(c1), "+f"(c2), "+f"(c3)
        : "r"(a0), "r"(a1), "r"(a2), "r"(a3), "r"(b0), "r"(b1));
}
__device__ __forceinline__ uint16_t f2e4m3x2(float lo, float hi) {
    uint16_t r;
    asm("cvt.rn.satfinite.e4m3x2.f32 %0, %1, %2;" : "=h"(r) : "f"(hi), "f"(lo));
    return r;
}

// ---------------- GroupNorm stats, phase 1: 512 partial reductions ----------------
__global__ void gn_stats1_kernel(const float* __restrict__ x) {
    int bg   = blockIdx.x >> 2;
    int part = blockIdx.x & 3;
    int b  = bg / NGROUPS;
    int g  = bg % NGROUPS;
    const float* base = x + (size_t)b * HW * C_DIM + g * GSIZE;

    float s = 0.f, ss = 0.f;
    for (int p = part * 1024 + threadIdx.x; p < (part + 1) * 1024; p += blockDim.x) {
        const float4* v4 = (const float4*)(base + (size_t)p * C_DIM);
        #pragma unroll
        for (int j = 0; j < 4; j++) {
            float4 v = v4[j];
            s  += v.x + v.y + v.z + v.w;
            ss += v.x*v.x + v.y*v.y + v.z*v.z + v.w*v.w;
        }
    }
    __shared__ float shs[8], shss[8];
    int lane = threadIdx.x & 31, wid = threadIdx.x >> 5;
    #pragma unroll
    for (int o = 16; o > 0; o >>= 1) {
        s  += __shfl_xor_sync(0xffffffffu, s,  o);
        ss += __shfl_xor_sync(0xffffffffu, ss, o);
    }
    if (lane == 0) { shs[wid] = s; shss[wid] = ss; }
    __syncthreads();
    if (threadIdx.x == 0) {
        float ts = 0.f, tss = 0.f;
        #pragma unroll
        for (int i = 0; i < 8; i++) { ts += shs[i]; tss += shss[i]; }
        g_ps[blockIdx.x * 2]     = ts;
        g_ps[blockIdx.x * 2 + 1] = tss;
    }
}

// ---------------- GroupNorm stats, phase 2: finalize ----------------
__global__ void gn_stats2_kernel() {
    int i = threadIdx.x;
    float ts = 0.f, tss = 0.f;
    #pragma unroll
    for (int p = 0; p < 4; p++) {
        ts  += g_ps[(i * 4 + p) * 2];
        tss += g_ps[(i * 4 + p) * 2 + 1];
    }
    const float invn = 1.0f / (float)(HW * GSIZE);
    float mean = ts * invn;
    float var  = tss * invn - mean * mean;
    g_mean[i] = mean;
    g_rstd[i] = rsqrtf(var + EPS);
}

// ---------------- GroupNorm apply (writes bf16 hn) ----------------
__global__ void gn_apply_kernel(const float* __restrict__ x,
                                const float* __restrict__ scale,
                                const float* __restrict__ bias) {
    size_t i = (size_t)blockIdx.x * blockDim.x + threadIdx.x;
    int    c4 = (int)(i % (C_DIM / 4));
    size_t t  = i / (C_DIM / 4);
    int    b  = (int)(t / HW);
    int    g  = (c4 * 4) / GSIZE;

    float mean = g_mean[b * NGROUPS + g];
    float rstd = g_rstd[b * NGROUPS + g];
    float4 xv = ((const float4*)x)[i];
    float4 sc = ((const float4*)scale)[c4];
    float4 bi = ((const float4*)bias)[c4];
    float r0 = (xv.x - mean) * rstd * sc.x + bi.x;
    float r1 = (xv.y - mean) * rstd * sc.y + bi.y;
    float r2 = (xv.z - mean) * rstd * sc.z + bi.z;
    float r3 = (xv.w - mean) * rstd * sc.w + bi.w;
    __nv_bfloat162* o = (__nv_bfloat162*)(g_hn + i * 4);
    o[0] = __floats2bfloat162_rn(r0, r1);
    o[1] = __floats2bfloat162_rn(r2, r3);
}

// ---------------- weight prep + rowsum zero ----------------
__global__ void prep_weights_kernel(const float* __restrict__ wq,
                                    const float* __restrict__ wk,
                                    const float* __restrict__ wv,
                                    const float* __restrict__ wo,
                                    const float* __restrict__ bq,
                                    const float* __restrict__ bk,
                                    const float* __restrict__ bv) {
    int i = blockIdx.x * blockDim.x + threadIdx.x;  // i = k*512+n
    int k = i >> 9, n = i & 511;
    g_wqkv[(n)        * C_DIM + k] = __float2bfloat16_rn(wq[i]);
    g_wqkv[(n + 512)  * C_DIM + k] = __float2bfloat16_rn(wk[i]);
    g_wqkv[(n + 1024) * C_DIM + k] = __float2bfloat16_rn(wv[i]);
    g_wo  [n * C_DIM + k]          = __float2bfloat16_rn(wo[i]);
    if (i < 512) {
        g_bqkv[i]        = bq[i];
        g_bqkv[i + 512]  = bk[i];
        g_bqkv[i + 1024] = bv[i];
    }
    if (i < NTOK) g_rowsum[i] = 0.f;
}

// ---------------- tensor-core GEMM, 64x128 tile, 3 CTAs/SM ----------------
// OUTMODE: 0 = fp32, 1 = bf16, 2 = QKV split (q,k -> e4m3; v -> g_v bf16)
// FP8: e4m3 mma; A/B viewed as b16 (K, lda, ldb in b16 units)
// BMODE 0: B stored [N,K]; BMODE 1: B stored [K,N]
// BM=64, BN=128, BK=32; 8 warps (2x4), 32x32 warp tile, 3-stage cp.async.
template<int BMODE, int OUTMODE, bool HAS_BIAS, bool HAS_RES, bool EXP_OUT, bool ROW_SCALE, bool FP8>
__global__ void __launch_bounds__(256, 3)
gemm_tc(const bf16* __restrict__ A, const bf16* __restrict__ B,
        const float* __restrict__ bias, const float* __restrict__ res,
        void* __restrict__ Cout,
        int M, int N, int K, int lda, int ldb, float alpha,
        size_t sA, size_t sB, size_t sC) {
    constexpr int BN = 128, BK = 32;
    constexpr int NSTAGE = 3;
    constexpr int ASTR = 40;
    constexpr int BSTR = (BMODE == 0) ? 40 : 136;
    constexpr int BROWS = (BMODE == 0) ? 128 : 32;
    constexpr int ASTAGE_B = BM * ASTR * 2;
    constexpr int BSTAGE_B = BROWS * BSTR * 2;

    __shared__ __align__(16) bf16 As[NSTAGE][BM * ASTR];
    __shared__ __align__(16) bf16 Bs[NSTAGE][BROWS * BSTR];
    __shared__ float srow[BM];

    A += (size_t)blockIdx.z * sA;
    B += (size_t)blockIdx.z * sB;

    const int bm = blockIdx.y * BM;
    const int bn = blockIdx.x * BN;
    const int tid  = threadIdx.x;
    const int lane = tid & 31;
    const int wid  = tid >> 5;
    const int g    = lane >> 2;
    const int t    = lane & 3;
    const int wm   = wid >> 2;      // 0..1 -> m offset *32
    const int wn   = wid & 3;       // 0..3 -> n offset *32

    const uint32_t uAs = smem_u32(&As[0][0]);
    const uint32_t uBs = smem_u32(&Bs[0][0]);

    if (EXP_OUT) { if (tid < BM) srow[tid] = 0.f; }

    float acc[2][4][4];
    #pragma unroll
    for (int i = 0; i < 2; i++)
        #pragma unroll
        for (int j = 0; j < 4; j++)
            #pragma unroll
            for (int r = 0; r < 4; r++) acc[i][j][r] = 0.f;

    auto load_stage = [&](int stage, int k0) {
        {   // A: 64 rows x 32 b16 = 256 x 16B chunks -> 1 per thread
            int row = tid >> 2, kc = tid & 3;
            CP_ASYNC16(uAs + stage * ASTAGE_B + (row * ASTR + kc * 8) * 2,
                       A + (size_t)(bm + row) * lda + k0 + kc * 8);
        }
        if (BMODE == 0) {
            #pragma unroll
            for (int i = 0; i < 2; i++) {
                int c = tid + i * 256;
                int row = c >> 2, kc = c & 3;
                CP_ASYNC16(uBs + stage * BSTAGE_B + (row * BSTR + kc * 8) * 2,
                           B + (size_t)(bn + row) * ldb + k0 + kc * 8);
            }
        } else {
            #pragma unroll
            for (int i = 0; i < 2; i++) {
                int c = tid + i * 256;
                int row = c >> 4, nc = c & 15;
                CP_ASYNC16(uBs + stage * BSTAGE_B + (row * BSTR + nc * 8) * 2,
                           B + (size_t)(k0 + row) * ldb + bn + nc * 8);
            }
        }
        CP_COMMIT();
    };

    const int nIter = K / BK;
    load_stage(0, 0);
    if (nIter > 1) load_stage(1, BK);

    const int a_row = (lane & 15);
    const int a_kc  = (lane >> 4);
    const int bnk_r = (lane & 7) + ((lane >> 4) << 3);
    const int bnk_k = (lane >> 3) & 1;
    const int bkn_r = (lane & 7) + (((lane >> 3) & 1) << 3);
    const int bkn_n = (lane >> 4);

    int stage = 0;
    for (int it = 0; it < nIter; it++) {
        if (it + 1 < nIter) {
            asm volatile("cp.async.wait_group 1;");
        } else {
            asm volatile("cp.async.wait_group 0;");
        }
        __syncthreads();

        if (it + 2 < nIter) {
            int ls = stage + 2; if (ls >= NSTAGE) ls -= NSTAGE;
            load_stage(ls, (it + 2) * BK);
        }

        const uint32_t aBase = uAs + stage * ASTAGE_B;
        const uint32_t bBase = uBs + stage * BSTAGE_B;

        #pragma unroll
        for (int ks = 0; ks < 2; ks++) {
            uint32_t a[2][4];
            #pragma unroll
            for (int mt = 0; mt < 2; mt++) {
                uint32_t addr = aBase +
                    ((wm * 32 + mt * 16 + a_row) * ASTR + ks * 16 + a_kc * 8) * 2;
                LDSM4(a[mt][0], a[mt][1], a[mt][2], a[mt][3], addr);
            }
            uint32_t bq[2][4];
            #pragma unroll
            for (int h = 0; h < 2; h++) {
                if (BMODE == 0) {
                    uint32_t addr = bBase +
                        ((wn * 32 + h * 16 + bnk_r) * BSTR + ks * 16 + bnk_k * 8) * 2;
                    LDSM4(bq[h][0], bq[h][1], bq[h][2], bq[h][3], addr);
                } else {
                    uint32_t addr = bBase +
                        ((ks * 16 + bkn_r) * BSTR + wn * 32 + h * 16 + bkn_n * 8) * 2;
                    LDSM4T(bq[h][0], bq[h][1], bq[h][2], bq[h][3], addr);
                }
            }
            #pragma unroll
            for (int mt = 0; mt < 2; mt++)
                #pragma unroll
                for (int nt = 0; nt < 4; nt++) {
                    if (FP8)
                        mma_e4m3(acc[mt][nt][0], acc[mt][nt][1], acc[mt][nt][2], acc[mt][nt][3],
                                 a[mt][0], a[mt][1], a[mt][2], a[mt][3],
                                 bq[nt >> 1][(nt & 1) * 2], bq[nt >> 1][(nt & 1) * 2 + 1]);
                    else
                        mma_bf16(acc[mt][nt][0], acc[mt][nt][1], acc[mt][nt][2], acc[mt][nt][3],
                                 a[mt][0], a[mt][1], a[mt][2], a[mt][3],
                                 bq[nt >> 1][(nt & 1) * 2], bq[nt >> 1][(nt & 1) * 2 + 1]);
                }
        }
        stage++; if (stage >= NSTAGE) stage = 0;
    }

    // epilogue
    #pragma unroll
    for (int mt = 0; mt < 2; mt++) {
        int r0 = bm + wm * 32 + mt * 16 + g;
        float inv0, inv1;
        if (ROW_SCALE) {
            inv0 = 1.0f / g_rowsum[blockIdx.z * HW + r0];
            inv1 = 1.0f / g_rowsum[blockIdx.z * HW + r0 + 8];
        }
        float s0 = 0.f, s1 = 0.f;
        #pragma unroll
        for (int nt = 0; nt < 4; nt++) {
            int col = bn + wn * 32 + nt * 8 + 2 * t;
            float2 bb = make_float2(0.f, 0.f);
            if (HAS_BIAS) bb = *(const float2*)(bias + col);

            float v0 = acc[mt][nt][0] * alpha + bb.x;
            float v1 = acc[mt][nt][1] * alpha + bb.y;
            float v2 = acc[mt][nt][2] * alpha + bb.x;
            float v3 = acc[mt][nt][3] * alpha + bb.y;
            if (EXP_OUT) {
                v0 = __expf(v0); v1 = __expf(v1);
                v2 = __expf(v2); v3 = __expf(v3);
                s0 += v0 + v1; s1 += v2 + v3;
            }
            if (ROW_SCALE) {
                v0 *= inv0; v1 *= inv0; v2 *= inv1; v3 *= inv1;
            }
            if (HAS_RES) {
                const float* rp = res + (size_t)blockIdx.z * sC;
                float2 ra = *(const float2*)(rp + (size_t)r0 * N + col);
                float2 rb = *(const float2*)(rp + (size_t)(r0 + 8) * N + col);
                v0 += ra.x; v1 += ra.y; v2 += rb.x; v3 += rb.y;
            }
            if (OUTMODE == 2) {
                if (bn >= 1024) {
                    int c = col - 1024;
                    *(__nv_bfloat162*)(g_v + (size_t)r0 * C_DIM + c)       = __floats2bfloat162_rn(v0, v1);
                    *(__nv_bfloat162*)(g_v + (size_t)(r0 + 8) * C_DIM + c) = __floats2bfloat162_rn(v2, v3);
                } else {
                    uint8_t* dst = (bn >= 512) ? g_k8 : g_q8;
                    int c = col - ((bn >= 512) ? 512 : 0);
                    *(uint16_t*)(dst + (size_t)r0 * C_DIM + c)       = f2e4m3x2(v0, v1);
                    *(uint16_t*)(dst + (size_t)(r0 + 8) * C_DIM + c) = f2e4m3x2(v2, v3);
                }
            } else if (OUTMODE == 1) {
                bf16* C = (bf16*)Cout + (size_t)blockIdx.z * sC;
                *(__nv_bfloat162*)(C + (size_t)r0 * N + col)       = __floats2bfloat162_rn(v0, v1);
                *(__nv_bfloat162*)(C + (size_t)(r0 + 8) * N + col) = __floats2bfloat162_rn(v2, v3);
            } else {
                float* C = (float*)Cout + (size_t)blockIdx.z * sC;
                *(float2*)(C + (size_t)r0 * N + col)       = make_float2(v0, v1);
                *(float2*)(C + (size_t)(r0 + 8) * N + col) = make_float2(v2, v3);
            }
        }
        if (EXP_OUT) {
            s0 += __shfl_xor_sync(0xffffffffu, s0, 1);
            s0 += __shfl_xor_sync(0xffffffffu, s0, 2);
            s1 += __shfl_xor_sync(0xffffffffu, s1, 1);
            s1 += __shfl_xor_sync(0xffffffffu, s1, 2);
            if (t == 0) {
                atomicAdd(&srow[wm * 32 + mt * 16 + g], s0);
                atomicAdd(&srow[wm * 32 + mt * 16 + g + 8], s1);
            }
        }
    }
    if (EXP_OUT) {
        __syncthreads();
        if (tid < BM)
            atomicAdd(&g_rowsum[blockIdx.z * HW + bm + tid], srow[tid]);
    }
}

// ---------------- launch ----------------
extern "C" void kernel_launch(void* const* d_in, const int* in_sizes, int n_in,
                              void* d_out, int out_size) {
    const float* x        = (const float*)d_in[0];
    const float* gn_scale = (const float*)d_in[1];
    const float* gn_bias  = (const float*)d_in[2];
    const float* wq = (const float*)d_in[3];  const float* bq = (const float*)d_in[4];
    const float* wk = (const float*)d_in[5];  const float* bk = (const float*)d_in[6];
    const float* wv = (const float*)d_in[7];  const float* bv = (const float*)d_in[8];
    const float* wo = (const float*)d_in[9];  const float* bo = (const float*)d_in[10];
    float* out = (float*)d_out;

    bf16 *hn, *s, *o, *v, *wqkvp, *wop;
    uint8_t *q8, *k8;
    float *bqkvp;
    cudaGetSymbolAddress((void**)&hn,    g_hn);
    cudaGetSymbolAddress((void**)&q8,    g_q8);
    cudaGetSymbolAddress((void**)&k8,    g_k8);
    cudaGetSymbolAddress((void**)&v,     g_v);
    cudaGetSymbolAddress((void**)&s,     g_s);
    cudaGetSymbolAddress((void**)&o,     g_o);
    cudaGetSymbolAddress((void**)&wqkvp, g_wqkv);
    cudaGetSymbolAddress((void**)&wop,   g_wo);
    cudaGetSymbolAddress((void**)&bqkvp, g_bqkv);

    // 1) GroupNorm (two-phase stats) + weight prep (also zeros g_rowsum)
    gn_stats1_kernel<<<BATCH * NGROUPS * 4, 256>>>(x);
    gn_stats2_kernel<<<1, BATCH * NGROUPS>>>();
    gn_apply_kernel<<<(NTOK * C_DIM / 4) / 256, 256>>>(x, gn_scale, gn_bias);
    prep_weights_kernel<<<(C_DIM * C_DIM) / 256, 256>>>(wq, wk, wv, wo, bq, bk, bv);

    dim3 blk(256);
    // 2) fused QKV projection; epilogue splits q,k -> e4m3, v -> bf16
    dim3 gqkv(QKV_N / 128, NTOK / BM, 1);
    gemm_tc<0, 2, true, false, false, false, false><<<gqkv, blk>>>(
        hn, wqkvp, bqkvp, nullptr, nullptr,
        NTOK, QKV_N, C_DIM, C_DIM, C_DIM, 1.0f, 0, 0, 0);

    // 3) P' = exp((Q @ K^T) * scale) in e4m3 inputs; bf16 out; accumulates g_rowsum
    dim3 gs(HW / 128, HW / BM, BATCH);
    gemm_tc<0, 1, false, false, true, false, true><<<gs, blk>>>(
        (const bf16*)q8, (const bf16*)k8, nullptr, nullptr, s,
        HW, HW, C_DIM / 2, C_DIM / 2, C_DIM / 2, SM_SCALE,
        (size_t)HW * (C_DIM / 2), (size_t)HW * (C_DIM / 2), (size_t)HW * HW);

    // 4) O = (P' @ V) / rowsum, batched; V stored [tok][512] -> BMODE 1
    dim3 gpv(C_DIM / 128, HW / BM, BATCH);
    gemm_tc<1, 1, false, false, false, true, false><<<gpv, blk>>>(
        s, v, nullptr, nullptr, o,
        HW, C_DIM, HW, HW, C_DIM, 1.0f,
        (size_t)HW * HW, (size_t)HW * C_DIM, (size_t)HW * C_DIM);

    // 5) out = x + O @ wo + bo ; fp32 out
    dim3 gproj(C_DIM / 128, NTOK / BM, 1);
    gemm_tc<0, 0, true, true, false, false, false><<<gproj, blk>>>(
        o, wop, bo, x, out,
        NTOK, C_DIM, C_DIM, C_DIM, C_DIM, 1.0f, 0, 0, 0);
}

// round 17
// speedup vs baseline: 1.0796x; 1.0796x over previous
#include <cuda_runtime.h>
#include <cuda_bf16.h>
#include <math_constants.h>
#include <cstdint>

// ---------------- problem constants ----------------
#define C_DIM   512
#define NGROUPS 32
#define GSIZE   16
#define BATCH   4
#define HW      4096
#define NTOK    16384
#define EPS     1e-6f
#define SM_SCALE 0.04419417382415922f   // 512^-0.5
#define QKV_N   1536

typedef __nv_bfloat16 bf16;

// ---------------- device scratch ----------------
__device__ float   g_ps  [BATCH * NGROUPS * 4 * 2];   // partial GN sums
__device__ float   g_mean[BATCH * NGROUPS];
__device__ float   g_rstd[BATCH * NGROUPS];
__device__ bf16    g_hn [NTOK * C_DIM];
__device__ uint8_t g_q8 [(size_t)NTOK * C_DIM];       // e4m3 Q
__device__ uint8_t g_k8 [(size_t)NTOK * C_DIM];       // e4m3 K
__device__ bf16    g_v  [(size_t)NTOK * C_DIM];       // bf16 V
__device__ bf16    g_s  [(size_t)BATCH * HW * HW];    // 128 MB exp(scores)
__device__ bf16    g_o  [NTOK * C_DIM];
__device__ bf16    g_wqkv[QKV_N * C_DIM];             // [n][k]
__device__ bf16    g_wo  [C_DIM * C_DIM];             // [n][k]
__device__ float   g_bqkv[QKV_N];
__device__ float   g_rowsum[NTOK];

// ---------------- helpers ----------------
__device__ __forceinline__ uint32_t smem_u32(const void* p) {
    return (uint32_t)__cvta_generic_to_shared(p);
}
#define CP_ASYNC16(dst, src) \
    asm volatile("cp.async.cg.shared.global [%0], [%1], 16;" :: "r"(dst), "l"(src))
#define CP_COMMIT() asm volatile("cp.async.commit_group;")

#define LDSM4(r0,r1,r2,r3, addr) \
    asm volatile("ldmatrix.sync.aligned.m8n8.x4.shared.b16 {%0,%1,%2,%3}, [%4];" \
        : "=r"(r0),"=r"(r1),"=r"(r2),"=r"(r3) : "r"(addr))
#define LDSM4T(r0,r1,r2,r3, addr) \
    asm volatile("ldmatrix.sync.aligned.m8n8.x4.trans.shared.b16 {%0,%1,%2,%3}, [%4];" \
        : "=r"(r0),"=r"(r1),"=r"(r2),"=r"(r3) : "r"(addr))

__device__ __forceinline__ void mma_bf16(float& c0, float& c1, float& c2, float& c3,
                                         uint32_t a0, uint32_t a1, uint32_t a2, uint32_t a3,
                                         uint32_t b0, uint32_t b1) {
    asm volatile(
        "mma.sync.aligned.m16n8k16.row.col.f32.bf16.bf16.f32 "
        "{%0,%1,%2,%3}, {%4,%5,%6,%7}, {%8,%9}, {%0,%1,%2,%3};"
        : "+f"(c0), "+f"(c1), "+f"(c2), "+f"(c3)
        : "r"(a0), "r"(a1), "r"(a2), "r"(a3), "r"(b0), "r"(b1));
}
__device__ __forceinline__ void mma_e4m3(float& c0, float& c1, float& c2, float& c3,
                                         uint32_t a0, uint32_t a1, uint32_t a2, uint32_t a3,
                                         uint32_t b0, uint32_t b1) {
    asm volatile(
        "mma.sync.aligned.m16n8k32.row.col.f32.e4m3.e4m3.f32 "
        "{%0,%1,%2,%3}, {%4,%5,%6,%7}, {%8,%9}, {%0,%1,%2,%3};"
        : "+f"(c0), "+f"(c1), "+f"(c2), "+f"(c3)
        : "r"(a0), "r"(a1), "r"(a2), "r"(a3), "r"(b0), "r"(b1));
}
__device__ __forceinline__ uint16_t f2e4m3x2(float lo, float hi) {
    uint16_t r;
    asm("cvt.rn.satfinite.e4m3x2.f32 %0, %1, %2;" : "=h"(r) : "f"(hi), "f"(lo));
    return r;
}

// ---------------- GroupNorm stats, phase 1: 512 partial reductions ----------------
__global__ void gn_stats1_kernel(const float* __restrict__ x) {
    int bg   = blockIdx.x >> 2;
    int part = blockIdx.x & 3;
    int b  = bg / NGROUPS;
    int g  = bg % NGROUPS;
    const float* base = x + (size_t)b * HW * C_DIM + g * GSIZE;

    float s = 0.f, ss = 0.f;
    for (int p = part * 1024 + threadIdx.x; p < (part + 1) * 1024; p += blockDim.x) {
        const float4* v4 = (const float4*)(base + (size_t)p * C_DIM);
        #pragma unroll
        for (int j = 0; j < 4; j++) {
            float4 v = v4[j];
            s  += v.x + v.y + v.z + v.w;
            ss += v.x*v.x + v.y*v.y + v.z*v.z + v.w*v.w;
        }
    }
    __shared__ float shs[8], shss[8];
    int lane = threadIdx.x & 31, wid = threadIdx.x >> 5;
    #pragma unroll
    for (int o = 16; o > 0; o >>= 1) {
        s  += __shfl_xor_sync(0xffffffffu, s,  o);
        ss += __shfl_xor_sync(0xffffffffu, ss, o);
    }
    if (lane == 0) { shs[wid] = s; shss[wid] = ss; }
    __syncthreads();
    if (threadIdx.x == 0) {
        float ts = 0.f, tss = 0.f;
        #pragma unroll
        for (int i = 0; i < 8; i++) { ts += shs[i]; tss += shss[i]; }
        g_ps[blockIdx.x * 2]     = ts;
        g_ps[blockIdx.x * 2 + 1] = tss;
    }
}

// ---------------- GroupNorm stats, phase 2: finalize ----------------
__global__ void gn_stats2_kernel() {
    int i = threadIdx.x;
    float ts = 0.f, tss = 0.f;
    #pragma unroll
    for (int p = 0; p < 4; p++) {
        ts  += g_ps[(i * 4 + p) * 2];
        tss += g_ps[(i * 4 + p) * 2 + 1];
    }
    const float invn = 1.0f / (float)(HW * GSIZE);
    float mean = ts * invn;
    float var  = tss * invn - mean * mean;
    g_mean[i] = mean;
    g_rstd[i] = rsqrtf(var + EPS);
}

// ---------------- GroupNorm apply (writes bf16 hn) ----------------
__global__ void gn_apply_kernel(const float* __restrict__ x,
                                const float* __restrict__ scale,
                                const float* __restrict__ bias) {
    size_t i = (size_t)blockIdx.x * blockDim.x + threadIdx.x;
    int    c4 = (int)(i % (C_DIM / 4));
    size_t t  = i / (C_DIM / 4);
    int    b  = (int)(t / HW);
    int    g  = (c4 * 4) / GSIZE;

    float mean = g_mean[b * NGROUPS + g];
    float rstd = g_rstd[b * NGROUPS + g];
    float4 xv = ((const float4*)x)[i];
    float4 sc = ((const float4*)scale)[c4];
    float4 bi = ((const float4*)bias)[c4];
    float r0 = (xv.x - mean) * rstd * sc.x + bi.x;
    float r1 = (xv.y - mean) * rstd * sc.y + bi.y;
    float r2 = (xv.z - mean) * rstd * sc.z + bi.z;
    float r3 = (xv.w - mean) * rstd * sc.w + bi.w;
    __nv_bfloat162* o = (__nv_bfloat162*)(g_hn + i * 4);
    o[0] = __floats2bfloat162_rn(r0, r1);
    o[1] = __floats2bfloat162_rn(r2, r3);
}

// ---------------- weight prep + rowsum zero ----------------
__global__ void prep_weights_kernel(const float* __restrict__ wq,
                                    const float* __restrict__ wk,
                                    const float* __restrict__ wv,
                                    const float* __restrict__ wo,
                                    const float* __restrict__ bq,
                                    const float* __restrict__ bk,
                                    const float* __restrict__ bv) {
    int i = blockIdx.x * blockDim.x + threadIdx.x;  // i = k*512+n
    int k = i >> 9, n = i & 511;
    g_wqkv[(n)        * C_DIM + k] = __float2bfloat16_rn(wq[i]);
    g_wqkv[(n + 512)  * C_DIM + k] = __float2bfloat16_rn(wk[i]);
    g_wqkv[(n + 1024) * C_DIM + k] = __float2bfloat16_rn(wv[i]);
    g_wo  [n * C_DIM + k]          = __float2bfloat16_rn(wo[i]);
    if (i < 512) {
        g_bqkv[i]        = bq[i];
        g_bqkv[i + 512]  = bk[i];
        g_bqkv[i + 1024] = bv[i];
    }
    if (i < NTOK) g_rowsum[i] = 0.f;
}

// ---------------- tensor-core GEMM (4-stage cp.async, wait_group 2) ----------------
// OUTMODE: 0 = fp32, 1 = bf16, 2 = QKV split (q,k -> e4m3; v -> g_v bf16)
// FP8: e4m3 mma; A/B viewed as b16 (K, lda, ldb in b16 units)
// BMODE 0: B stored [N,K]; BMODE 1: B stored [K,N]
// 128x128 tile (BK=32 b16 units), 8 warps (2x4), 64x32 warp tile.
template<int BMODE, int OUTMODE, bool HAS_BIAS, bool HAS_RES, bool EXP_OUT, bool ROW_SCALE, bool FP8>
__global__ void __launch_bounds__(256, 2)
gemm_tc(const bf16* __restrict__ A, const bf16* __restrict__ B,
        const float* __restrict__ bias, const float* __restrict__ res,
        void* __restrict__ Cout,
        int M, int N, int K, int lda, int ldb, float alpha,
        size_t sA, size_t sB, size_t sC) {
    constexpr int BM = 128, BN = 128, BK = 32;
    constexpr int NSTAGE = 4;
    constexpr int ASTR = 40;
    constexpr int BSTR = (BMODE == 0) ? 40 : 136;
    constexpr int BROWS = (BMODE == 0) ? 128 : 32;
    constexpr int ASTAGE_B = BM * ASTR * 2;
    constexpr int BSTAGE_B = BROWS * BSTR * 2;

    __shared__ __align__(16) bf16 As[NSTAGE][BM * ASTR];
    __shared__ __align__(16) bf16 Bs[NSTAGE][BROWS * BSTR];
    __shared__ float srow[BM];

    A += (size_t)blockIdx.z * sA;
    B += (size_t)blockIdx.z * sB;

    const int bm = blockIdx.y * BM;
    const int bn = blockIdx.x * BN;
    const int tid  = threadIdx.x;
    const int lane = tid & 31;
    const int wid  = tid >> 5;
    const int g    = lane >> 2;
    const int t    = lane & 3;
    const int wm   = wid >> 2;
    const int wn   = wid & 3;

    const uint32_t uAs = smem_u32(&As[0][0]);
    const uint32_t uBs = smem_u32(&Bs[0][0]);

    if (EXP_OUT) { if (tid < BM) srow[tid] = 0.f; }

    float acc[4][4][4];
    #pragma unroll
    for (int i = 0; i < 4; i++)
        #pragma unroll
        for (int j = 0; j < 4; j++)
            #pragma unroll
            for (int r = 0; r < 4; r++) acc[i][j][r] = 0.f;

    auto load_stage = [&](int stage, int k0) {
        #pragma unroll
        for (int i = 0; i < 2; i++) {
            int c = tid + i * 256;
            int row = c >> 2, kc = c & 3;
            CP_ASYNC16(uAs + stage * ASTAGE_B + (row * ASTR + kc * 8) * 2,
                       A + (size_t)(bm + row) * lda + k0 + kc * 8);
        }
        if (BMODE == 0) {
            #pragma unroll
            for (int i = 0; i < 2; i++) {
                int c = tid + i * 256;
                int row = c >> 2, kc = c & 3;
                CP_ASYNC16(uBs + stage * BSTAGE_B + (row * BSTR + kc * 8) * 2,
                           B + (size_t)(bn + row) * ldb + k0 + kc * 8);
            }
        } else {
            #pragma unroll
            for (int i = 0; i < 2; i++) {
                int c = tid + i * 256;
                int row = c >> 4, nc = c & 15;
                CP_ASYNC16(uBs + stage * BSTAGE_B + (row * BSTR + nc * 8) * 2,
                           B + (size_t)(k0 + row) * ldb + bn + nc * 8);
            }
        }
        CP_COMMIT();
    };

    const int nIter = K / BK;
    // preload up to 3 stages
    load_stage(0, 0);
    if (nIter > 1) load_stage(1, BK);
    if (nIter > 2) load_stage(2, 2 * BK);

    const int a_row = (lane & 15);
    const int a_kc  = (lane >> 4);
    const int bnk_r = (lane & 7) + ((lane >> 4) << 3);
    const int bnk_k = (lane >> 3) & 1;
    const int bkn_r = (lane & 7) + (((lane >> 3) & 1) << 3);
    const int bkn_n = (lane >> 4);

    int stage = 0;
    for (int it = 0; it < nIter; it++) {
        if (it + 2 < nIter) {
            asm volatile("cp.async.wait_group 2;");
        } else if (it + 1 < nIter) {
            asm volatile("cp.async.wait_group 1;");
        } else {
            asm volatile("cp.async.wait_group 0;");
        }
        __syncthreads();

        if (it + 3 < nIter) {
            int ls = stage + 3; if (ls >= NSTAGE) ls -= NSTAGE;
            load_stage(ls, (it + 3) * BK);
        }

        const uint32_t aBase = uAs + stage * ASTAGE_B;
        const uint32_t bBase = uBs + stage * BSTAGE_B;

        #pragma unroll
        for (int ks = 0; ks < 2; ks++) {
            uint32_t a[4][4];
            #pragma unroll
            for (int mt = 0; mt < 4; mt++) {
                uint32_t addr = aBase +
                    ((wm * 64 + mt * 16 + a_row) * ASTR + ks * 16 + a_kc * 8) * 2;
                LDSM4(a[mt][0], a[mt][1], a[mt][2], a[mt][3], addr);
            }
            uint32_t bq[2][4];
            #pragma unroll
            for (int h = 0; h < 2; h++) {
                if (BMODE == 0) {
                    uint32_t addr = bBase +
                        ((wn * 32 + h * 16 + bnk_r) * BSTR + ks * 16 + bnk_k * 8) * 2;
                    LDSM4(bq[h][0], bq[h][1], bq[h][2], bq[h][3], addr);
                } else {
                    uint32_t addr = bBase +
                        ((ks * 16 + bkn_r) * BSTR + wn * 32 + h * 16 + bkn_n * 8) * 2;
                    LDSM4T(bq[h][0], bq[h][1], bq[h][2], bq[h][3], addr);
                }
            }
            #pragma unroll
            for (int mt = 0; mt < 4; mt++)
                #pragma unroll
                for (int nt = 0; nt < 4; nt++) {
                    if (FP8)
                        mma_e4m3(acc[mt][nt][0], acc[mt][nt][1], acc[mt][nt][2], acc[mt][nt][3],
                                 a[mt][0], a[mt][1], a[mt][2], a[mt][3],
                                 bq[nt >> 1][(nt & 1) * 2], bq[nt >> 1][(nt & 1) * 2 + 1]);
                    else
                        mma_bf16(acc[mt][nt][0], acc[mt][nt][1], acc[mt][nt][2], acc[mt][nt][3],
                                 a[mt][0], a[mt][1], a[mt][2], a[mt][3],
                                 bq[nt >> 1][(nt & 1) * 2], bq[nt >> 1][(nt & 1) * 2 + 1]);
                }
        }
        stage++; if (stage >= NSTAGE) stage = 0;
    }

    // epilogue
    #pragma unroll
    for (int mt = 0; mt < 4; mt++) {
        int r0 = bm + wm * 64 + mt * 16 + g;
        float inv0, inv1;
        if (ROW_SCALE) {
            inv0 = 1.0f / g_rowsum[blockIdx.z * HW + r0];
            inv1 = 1.0f / g_rowsum[blockIdx.z * HW + r0 + 8];
        }
        float s0 = 0.f, s1 = 0.f;
        #pragma unroll
        for (int nt = 0; nt < 4; nt++) {
            int col = bn + wn * 32 + nt * 8 + 2 * t;
            float2 bb = make_float2(0.f, 0.f);
            if (HAS_BIAS) bb = *(const float2*)(bias + col);

            float v0 = acc[mt][nt][0] * alpha + bb.x;
            float v1 = acc[mt][nt][1] * alpha + bb.y;
            float v2 = acc[mt][nt][2] * alpha + bb.x;
            float v3 = acc[mt][nt][3] * alpha + bb.y;
            if (EXP_OUT) {
                v0 = __expf(v0); v1 = __expf(v1);
                v2 = __expf(v2); v3 = __expf(v3);
                s0 += v0 + v1; s1 += v2 + v3;
            }
            if (ROW_SCALE) {
                v0 *= inv0; v1 *= inv0; v2 *= inv1; v3 *= inv1;
            }
            if (HAS_RES) {
                const float* rp = res + (size_t)blockIdx.z * sC;
                float2 ra = *(const float2*)(rp + (size_t)r0 * N + col);
                float2 rb = *(const float2*)(rp + (size_t)(r0 + 8) * N + col);
                v0 += ra.x; v1 += ra.y; v2 += rb.x; v3 += rb.y;
            }
            if (OUTMODE == 2) {
                if (bn >= 1024) {
                    int c = col - 1024;
                    *(__nv_bfloat162*)(g_v + (size_t)r0 * C_DIM + c)       = __floats2bfloat162_rn(v0, v1);
                    *(__nv_bfloat162*)(g_v + (size_t)(r0 + 8) * C_DIM + c) = __floats2bfloat162_rn(v2, v3);
                } else {
                    uint8_t* dst = (bn >= 512) ? g_k8 : g_q8;
                    int c = col - ((bn >= 512) ? 512 : 0);
                    *(uint16_t*)(dst + (size_t)r0 * C_DIM + c)       = f2e4m3x2(v0, v1);
                    *(uint16_t*)(dst + (size_t)(r0 + 8) * C_DIM + c) = f2e4m3x2(v2, v3);
                }
            } else if (OUTMODE == 1) {
                bf16* C = (bf16*)Cout + (size_t)blockIdx.z * sC;
                *(__nv_bfloat162*)(C + (size_t)r0 * N + col)       = __floats2bfloat162_rn(v0, v1);
                *(__nv_bfloat162*)(C + (size_t)(r0 + 8) * N + col) = __floats2bfloat162_rn(v2, v3);
            } else {
                float* C = (float*)Cout + (size_t)blockIdx.z * sC;
                *(float2*)(C + (size_t)r0 * N + col)       = make_float2(v0, v1);
                *(float2*)(C + (size_t)(r0 + 8) * N + col) = make_float2(v2, v3);
            }
        }
        if (EXP_OUT) {
            s0 += __shfl_xor_sync(0xffffffffu, s0, 1);
            s0 += __shfl_xor_sync(0xffffffffu, s0, 2);
            s1 += __shfl_xor_sync(0xffffffffu, s1, 1);
            s1 += __shfl_xor_sync(0xffffffffu, s1, 2);
            if (t == 0) {
                atomicAdd(&srow[wm * 64 + mt * 16 + g], s0);
                atomicAdd(&srow[wm * 64 + mt * 16 + g + 8], s1);
            }
        }
    }
    if (EXP_OUT) {
        __syncthreads();
        if (tid < BM)
            atomicAdd(&g_rowsum[blockIdx.z * HW + bm + tid], srow[tid]);
    }
}

// ---------------- launch ----------------
extern "C" void kernel_launch(void* const* d_in, const int* in_sizes, int n_in,
                              void* d_out, int out_size) {
    const float* x        = (const float*)d_in[0];
    const float* gn_scale = (const float*)d_in[1];
    const float* gn_bias  = (const float*)d_in[2];
    const float* wq = (const float*)d_in[3];  const float* bq = (const float*)d_in[4];
    const float* wk = (const float*)d_in[5];  const float* bk = (const float*)d_in[6];
    const float* wv = (const float*)d_in[7];  const float* bv = (const float*)d_in[8];
    const float* wo = (const float*)d_in[9];  const float* bo = (const float*)d_in[10];
    float* out = (float*)d_out;

    bf16 *hn, *s, *o, *v, *wqkvp, *wop;
    uint8_t *q8, *k8;
    float *bqkvp;
    cudaGetSymbolAddress((void**)&hn,    g_hn);
    cudaGetSymbolAddress((void**)&q8,    g_q8);
    cudaGetSymbolAddress((void**)&k8,    g_k8);
    cudaGetSymbolAddress((void**)&v,     g_v);
    cudaGetSymbolAddress((void**)&s,     g_s);
    cudaGetSymbolAddress((void**)&o,     g_o);
    cudaGetSymbolAddress((void**)&wqkvp, g_wqkv);
    cudaGetSymbolAddress((void**)&wop,   g_wo);
    cudaGetSymbolAddress((void**)&bqkvp, g_bqkv);

    // 1) GroupNorm (two-phase stats) + weight prep (also zeros g_rowsum)
    gn_stats1_kernel<<<BATCH * NGROUPS * 4, 256>>>(x);
    gn_stats2_kernel<<<1, BATCH * NGROUPS>>>();
    gn_apply_kernel<<<(NTOK * C_DIM / 4) / 256, 256>>>(x, gn_scale, gn_bias);
    prep_weights_kernel<<<(C_DIM * C_DIM) / 256, 256>>>(wq, wk, wv, wo, bq, bk, bv);

    dim3 blk(256);
    // 2) fused QKV projection; epilogue splits q,k -> e4m3, v -> bf16
    dim3 gqkv(QKV_N / 128, NTOK / 128, 1);
    gemm_tc<0, 2, true, false, false, false, false><<<gqkv, blk>>>(
        hn, wqkvp, bqkvp, nullptr, nullptr,
        NTOK, QKV_N, C_DIM, C_DIM, C_DIM, 1.0f, 0, 0, 0);

    // 3) P' = exp((Q @ K^T) * scale) in e4m3 inputs; bf16 out; accumulates g_rowsum
    dim3 gs(HW / 128, HW / 128, BATCH);
    gemm_tc<0, 1, false, false, true, false, true><<<gs, blk>>>(
        (const bf16*)q8, (const bf16*)k8, nullptr, nullptr, s,
        HW, HW, C_DIM / 2, C_DIM / 2, C_DIM / 2, SM_SCALE,
        (size_t)HW * (C_DIM / 2), (size_t)HW * (C_DIM / 2), (size_t)HW * HW);

    // 4) O = (P' @ V) / rowsum, batched; V stored [tok][512] -> BMODE 1
    dim3 gpv(C_DIM / 128, HW / 128, BATCH);
    gemm_tc<1, 1, false, false, false, true, false><<<gpv, blk>>>(
        s, v, nullptr, nullptr, o,
        HW, C_DIM, HW, HW, C_DIM, 1.0f,
        (size_t)HW * HW, (size_t)HW * C_DIM, (size_t)HW * C_DIM);

    // 5) out = x + O @ wo + bo ; fp32 out
    dim3 gproj(C_DIM / 128, NTOK / 128, 1);
    gemm_tc<0, 0, true, true, false, false, false><<<gproj, blk>>>(
        o, wop, bo, x, out,
        NTOK, C_DIM, C_DIM, C_DIM, C_DIM, 1.0f, 0, 0, 0);
}